// round 1
// baseline (speedup 1.0000x reference)
#include <cuda_runtime.h>
#include <math.h>

// Problem constants
#define B_    4
#define L_    128
#define W_    128
#define D_    256
#define H_    8
#define DK_   32
#define MROWS (B_*L_*W_)      // 65536 rows for the projection / FC GEMMs
#define NBLH  (B_*L_*H_)      // 4096 attention blocks
#define OUT_ELEMS   ((size_t)MROWS * D_)         // 16777216
#define ATTN_ELEMS  ((size_t)NBLH * W_ * W_)     // 67108864

// Scratch (static device arrays: allocation-free per harness rules)
__device__ float g_qh[(size_t)NBLH * W_ * DK_];      // [b,l,h][w][dk], pre-scaled by 1/sqrt(DK)
__device__ float g_kh[(size_t)NBLH * W_ * DK_];
__device__ float g_vh[(size_t)NBLH * W_ * DK_];
__device__ float g_attnout[OUT_ELEMS];               // attention output back in [m][d] layout
__device__ float g_fc[OUT_ELEMS];                    // FC + residual, pre-LayerNorm

// ---------------------------------------------------------------------------
// Tiled SGEMM core: C[128x128] tile of X[M,256] * W^T (W is [N=256, K=256] row-major)
// 256 threads, 8x8 microtile per thread, BK=16.
// ---------------------------------------------------------------------------
struct GemmFrag { float acc[8][8]; int tm, tn; };

__device__ __forceinline__ void sgemm_tile(const float* __restrict__ X,
                                           const float* __restrict__ Wt,
                                           int m0, int n0, GemmFrag& f)
{
    __shared__ float As[16][128];
    __shared__ float Bs[16][128];

    const int tid = threadIdx.x;
    f.tm = (tid >> 4) << 3;   // 0..120
    f.tn = (tid & 15) << 3;   // 0..120

    #pragma unroll
    for (int i = 0; i < 8; i++)
        #pragma unroll
        for (int j = 0; j < 8; j++)
            f.acc[i][j] = 0.0f;

    for (int kt = 0; kt < 256; kt += 16) {
        // load 128x16 tiles of X and W, transposed into shared
        #pragma unroll
        for (int i = 0; i < 2; i++) {
            int v   = tid + i * 256;          // 0..511 (float4 index)
            int row = v >> 2;                 // 0..127
            int col = (v & 3) << 2;           // 0,4,8,12
            float4 xa = *(const float4*)&X[(size_t)(m0 + row) * 256 + kt + col];
            As[col + 0][row] = xa.x; As[col + 1][row] = xa.y;
            As[col + 2][row] = xa.z; As[col + 3][row] = xa.w;
            float4 xb = *(const float4*)&Wt[(size_t)(n0 + row) * 256 + kt + col];
            Bs[col + 0][row] = xb.x; Bs[col + 1][row] = xb.y;
            Bs[col + 2][row] = xb.z; Bs[col + 3][row] = xb.w;
        }
        __syncthreads();

        #pragma unroll
        for (int kk = 0; kk < 16; kk++) {
            float fa[8], fb[8];
            *(float4*)&fa[0] = *(const float4*)&As[kk][f.tm];
            *(float4*)&fa[4] = *(const float4*)&As[kk][f.tm + 4];
            *(float4*)&fb[0] = *(const float4*)&Bs[kk][f.tn];
            *(float4*)&fb[4] = *(const float4*)&Bs[kk][f.tn + 4];
            #pragma unroll
            for (int i = 0; i < 8; i++)
                #pragma unroll
                for (int j = 0; j < 8; j++)
                    f.acc[i][j] = fmaf(fa[i], fb[j], f.acc[i][j]);
        }
        __syncthreads();
    }
}

// ---------------------------------------------------------------------------
// QKV projection: z = 0/1/2 selects (q,Wq,bq)->g_qh (scaled), (k,..)->g_kh, (v,..)->g_vh
// Output layout: [blq(=b*L+l), h, w, dk]
// ---------------------------------------------------------------------------
__global__ __launch_bounds__(256, 2) void gemm_proj(
    const float* __restrict__ q,  const float* __restrict__ k,  const float* __restrict__ v,
    const float* __restrict__ Wq, const float* __restrict__ Wk, const float* __restrict__ Wv,
    const float* __restrict__ bq, const float* __restrict__ bk, const float* __restrict__ bv)
{
    const int z = blockIdx.z;
    const float* X    = (z == 0) ? q  : (z == 1) ? k  : v;
    const float* Wt   = (z == 0) ? Wq : (z == 1) ? Wk : Wv;
    const float* bias = (z == 0) ? bq : (z == 1) ? bk : bv;
    float*       out  = (z == 0) ? g_qh : (z == 1) ? g_kh : g_vh;
    const float scale = (z == 0) ? 0.17677669529663687f : 1.0f;  // 1/sqrt(32)

    const int m0 = blockIdx.x * 128;
    const int n0 = blockIdx.y * 128;

    GemmFrag f;
    sgemm_tile(X, Wt, m0, n0, f);

    #pragma unroll
    for (int i = 0; i < 8; i++) {
        int m   = m0 + f.tm + i;
        int blq = m >> 7;          // b*L + l
        int w   = m & 127;
        #pragma unroll
        for (int j = 0; j < 8; j++) {
            int n  = n0 + f.tn + j;
            int h  = n >> 5;
            int dk = n & 31;
            float val = (f.acc[i][j] + bias[n]) * scale;
            out[((((size_t)blq * H_) + h) * W_ + w) * DK_ + dk] = val;
        }
    }
}

// ---------------------------------------------------------------------------
// FC projection + residual: g_fc = g_attnout @ Wfc^T + bfc + resid
// ---------------------------------------------------------------------------
__global__ __launch_bounds__(256, 2) void gemm_fc(
    const float* __restrict__ Wfc, const float* __restrict__ bfc,
    const float* __restrict__ resid)
{
    const int m0 = blockIdx.x * 128;
    const int n0 = blockIdx.y * 128;

    GemmFrag f;
    sgemm_tile(g_attnout, Wfc, m0, n0, f);

    #pragma unroll
    for (int i = 0; i < 8; i++) {
        int m = m0 + f.tm + i;
        #pragma unroll
        for (int j = 0; j < 8; j++) {
            int n = n0 + f.tn + j;
            size_t idx = (size_t)m * 256 + n;
            g_fc[idx] = f.acc[i][j] + bfc[n] + resid[idx];
        }
    }
}

// ---------------------------------------------------------------------------
// Fused attention for one (b,l,h): S = Q K^T (Q pre-scaled), softmax,
// write attn to gmem, O = P V back to [m][d] layout.
// 256 threads. Dynamic shared: Qt[32][128], Kt[32][128], Vs[128][32], Ps[128][128]
// ---------------------------------------------------------------------------
#define SMEM_ATTN ((32*128 + 32*128 + 128*32 + 128*128) * 4)   // 114688 B

__global__ __launch_bounds__(256) void attn_kernel(float* __restrict__ attn_out)
{
    extern __shared__ float sm[];
    float* Qt = sm;            // [d][i]  32 x 128
    float* Kt = sm + 4096;     // [d][j]  32 x 128
    float* Vs = sm + 8192;     // [j][d] 128 x 32
    float* Ps = sm + 12288;    // [i][j] 128 x 128

    const int blk = blockIdx.x;                   // (b*L+l)*H + h
    const int tid = threadIdx.x;
    const float4* Qg = (const float4*)(g_qh + (size_t)blk * 4096);
    const float4* Kg = (const float4*)(g_kh + (size_t)blk * 4096);
    const float4* Vg = (const float4*)(g_vh + (size_t)blk * 4096);

    // Load Q,K transposed; V natural
    for (int idx = tid; idx < 1024; idx += 256) {
        int row = idx >> 3;            // 0..127
        int d4  = (idx & 7) << 2;      // 0..28
        float4 xq = Qg[idx];
        Qt[(d4 + 0) * 128 + row] = xq.x; Qt[(d4 + 1) * 128 + row] = xq.y;
        Qt[(d4 + 2) * 128 + row] = xq.z; Qt[(d4 + 3) * 128 + row] = xq.w;
        float4 xk = Kg[idx];
        Kt[(d4 + 0) * 128 + row] = xk.x; Kt[(d4 + 1) * 128 + row] = xk.y;
        Kt[(d4 + 2) * 128 + row] = xk.z; Kt[(d4 + 3) * 128 + row] = xk.w;
        ((float4*)Vs)[idx] = Vg[idx];
    }
    __syncthreads();

    // Phase 1: S = Q K^T, 8x8 microtile per thread
    const int tm = (tid >> 4) << 3;
    const int tn = (tid & 15) << 3;
    float p[8][8];
    #pragma unroll
    for (int i = 0; i < 8; i++)
        #pragma unroll
        for (int j = 0; j < 8; j++) p[i][j] = 0.0f;

    #pragma unroll 8
    for (int kk = 0; kk < 32; kk++) {
        float fa[8], fb[8];
        *(float4*)&fa[0] = *(const float4*)&Qt[kk * 128 + tm];
        *(float4*)&fa[4] = *(const float4*)&Qt[kk * 128 + tm + 4];
        *(float4*)&fb[0] = *(const float4*)&Kt[kk * 128 + tn];
        *(float4*)&fb[4] = *(const float4*)&Kt[kk * 128 + tn + 4];
        #pragma unroll
        for (int i = 0; i < 8; i++)
            #pragma unroll
            for (int j = 0; j < 8; j++)
                p[i][j] = fmaf(fa[i], fb[j], p[i][j]);
    }

    // Softmax per row: each row's 128 cols live in one 16-thread group (same tm)
    #pragma unroll
    for (int ii = 0; ii < 8; ii++) {
        float mx = p[ii][0];
        #pragma unroll
        for (int jj = 1; jj < 8; jj++) mx = fmaxf(mx, p[ii][jj]);
        #pragma unroll
        for (int o = 8; o >= 1; o >>= 1)
            mx = fmaxf(mx, __shfl_xor_sync(0xffffffffu, mx, o));
        float s = 0.0f;
        #pragma unroll
        for (int jj = 0; jj < 8; jj++) { p[ii][jj] = __expf(p[ii][jj] - mx); s += p[ii][jj]; }
        #pragma unroll
        for (int o = 8; o >= 1; o >>= 1)
            s += __shfl_xor_sync(0xffffffffu, s, o);
        float r = 1.0f / s;
        #pragma unroll
        for (int jj = 0; jj < 8; jj++) p[ii][jj] *= r;
    }

    // Write attn probabilities to gmem + shared Ps
    const size_t abase = (size_t)blk * 16384;
    #pragma unroll
    for (int ii = 0; ii < 8; ii++) {
        int i = tm + ii;
        float4 v0 = make_float4(p[ii][0], p[ii][1], p[ii][2], p[ii][3]);
        float4 v1 = make_float4(p[ii][4], p[ii][5], p[ii][6], p[ii][7]);
        *(float4*)&Ps[i * 128 + tn]     = v0;
        *(float4*)&Ps[i * 128 + tn + 4] = v1;
        *(float4*)&attn_out[abase + (size_t)i * 128 + tn]     = v0;
        *(float4*)&attn_out[abase + (size_t)i * 128 + tn + 4] = v1;
    }
    __syncthreads();

    // Phase 2: O = P V. Warp w owns rows {w, w+8, ..., w+120}; lane = d.
    const int warp = tid >> 5;
    const int lane = tid & 31;
    float acc[16];
    #pragma unroll
    for (int r = 0; r < 16; r++) acc[r] = 0.0f;

    for (int j = 0; j < 128; j += 4) {
        float v0 = Vs[(j + 0) * 32 + lane];
        float v1 = Vs[(j + 1) * 32 + lane];
        float v2 = Vs[(j + 2) * 32 + lane];
        float v3 = Vs[(j + 3) * 32 + lane];
        #pragma unroll
        for (int r = 0; r < 16; r++) {
            float4 pp = *(const float4*)&Ps[(warp + 8 * r) * 128 + j];
            acc[r] = fmaf(pp.x, v0, fmaf(pp.y, v1, fmaf(pp.z, v2, fmaf(pp.w, v3, acc[r]))));
        }
    }

    // Store O back to [m][d] layout: m = blq*128 + i, d = h*32 + lane
    const int blq = blk >> 3;
    const int h   = blk & 7;
    #pragma unroll
    for (int r = 0; r < 16; r++) {
        int i = warp + 8 * r;
        g_attnout[((size_t)(blq * 128 + i)) * 256 + h * 32 + lane] = acc[r];
    }
}

// ---------------------------------------------------------------------------
// LayerNorm: warp per row of 256
// ---------------------------------------------------------------------------
__global__ __launch_bounds__(256) void ln_kernel(const float* __restrict__ ln_w,
                                                 const float* __restrict__ ln_b,
                                                 float* __restrict__ out)
{
    const int row  = blockIdx.x * 8 + (threadIdx.x >> 5);
    const int lane = threadIdx.x & 31;
    const float* x = g_fc + (size_t)row * 256;

    float v[8];
    #pragma unroll
    for (int c = 0; c < 8; c++) v[c] = x[lane + 32 * c];

    float s = 0.0f;
    #pragma unroll
    for (int c = 0; c < 8; c++) s += v[c];
    #pragma unroll
    for (int o = 16; o >= 1; o >>= 1) s += __shfl_xor_sync(0xffffffffu, s, o);
    float mu = s * (1.0f / 256.0f);

    float var = 0.0f;
    #pragma unroll
    for (int c = 0; c < 8; c++) { float d = v[c] - mu; var = fmaf(d, d, var); }
    #pragma unroll
    for (int o = 16; o >= 1; o >>= 1) var += __shfl_xor_sync(0xffffffffu, var, o);
    float rstd = rsqrtf(var * (1.0f / 256.0f) + 1e-6f);

    #pragma unroll
    for (int c = 0; c < 8; c++) {
        int n = lane + 32 * c;
        out[(size_t)row * 256 + n] = (v[c] - mu) * rstd * ln_w[n] + ln_b[n];
    }
}

// ---------------------------------------------------------------------------
extern "C" void kernel_launch(void* const* d_in, const int* in_sizes, int n_in,
                              void* d_out, int out_size)
{
    const float* q    = (const float*)d_in[0];
    const float* k    = (const float*)d_in[1];
    const float* v    = (const float*)d_in[2];
    const float* Wq   = (const float*)d_in[3];
    const float* bq   = (const float*)d_in[4];
    const float* Wk   = (const float*)d_in[5];
    const float* bk   = (const float*)d_in[6];
    const float* Wv   = (const float*)d_in[7];
    const float* bv   = (const float*)d_in[8];
    const float* Wfc  = (const float*)d_in[9];
    const float* bfc  = (const float*)d_in[10];
    const float* ln_w = (const float*)d_in[11];
    const float* ln_b = (const float*)d_in[12];

    float* out  = (float*)d_out;                 // [B,L,W,D] normalized output
    float* attn = out + OUT_ELEMS;               // [B,L,H,W,W] attention probs

    static bool attr_set = false;
    if (!attr_set) {
        cudaFuncSetAttribute(attn_kernel, cudaFuncAttributeMaxDynamicSharedMemorySize, SMEM_ATTN);
        attr_set = true;
    }

    gemm_proj<<<dim3(512, 2, 3), 256>>>(q, k, v, Wq, Wk, Wv, bq, bk, bv);
    attn_kernel<<<NBLH, 256, SMEM_ATTN>>>(attn);
    gemm_fc<<<dim3(512, 2, 1), 256>>>(Wfc, bfc, q);
    ln_kernel<<<MROWS / 8, 256>>>(ln_w, ln_b, out);
}

// round 2
// speedup vs baseline: 2.4594x; 2.4594x over previous
#include <cuda_runtime.h>
#include <math.h>
#include <stdint.h>

// Problem constants
#define B_    4
#define L_    128
#define W_    128
#define D_    256
#define H_    8
#define DK_   32
#define MROWS (B_*L_*W_)      // 65536
#define NBLH  (B_*L_*H_)      // 4096
#define OUT_ELEMS   ((size_t)MROWS * D_)         // 16777216

// Scratch
__device__ float g_qh[(size_t)NBLH * W_ * DK_];   // [blq][h][w][dk], pre-scaled
__device__ float g_kh[(size_t)NBLH * W_ * DK_];
__device__ float g_vh[(size_t)NBLH * W_ * DK_];
__device__ float g_attnout[OUT_ELEMS];            // attention out, [m][d]

// ---------------------------------------------------------------------------
// tf32 helpers
// ---------------------------------------------------------------------------
__device__ __forceinline__ uint32_t f2tf(float x) {
    uint32_t r;
    asm("cvt.rna.tf32.f32 %0, %1;" : "=r"(r) : "f"(x));
    return r;
}

__device__ __forceinline__ void mma_tf32(float* d, const uint32_t* a, const uint32_t* b) {
    asm volatile(
        "mma.sync.aligned.m16n8k8.row.col.f32.tf32.tf32.f32 "
        "{%0,%1,%2,%3}, {%4,%5,%6,%7}, {%8,%9}, {%0,%1,%2,%3};"
        : "+f"(d[0]), "+f"(d[1]), "+f"(d[2]), "+f"(d[3])
        : "r"(a[0]), "r"(a[1]), "r"(a[2]), "r"(a[3]), "r"(b[0]), "r"(b[1]));
}

// ---------------------------------------------------------------------------
// Kernel A: QKV projection. C = X @ W^T + b, scatter to [blq][h][w][dk].
// Block tile 128x128, 8 warps (2x4), warp tile 64x32, BK=32.
// ---------------------------------------------------------------------------
__global__ __launch_bounds__(256) void gemm_proj(
    const float* __restrict__ q,  const float* __restrict__ k,  const float* __restrict__ v,
    const float* __restrict__ Wq, const float* __restrict__ Wk, const float* __restrict__ Wv,
    const float* __restrict__ bq, const float* __restrict__ bk, const float* __restrict__ bv)
{
    __shared__ uint32_t Asu[128 * 36];
    __shared__ uint32_t Bsu[128 * 36];

    const int z = blockIdx.z;
    const float* X    = (z == 0) ? q  : (z == 1) ? k  : v;
    const float* Wt   = (z == 0) ? Wq : (z == 1) ? Wk : Wv;
    const float* bias = (z == 0) ? bq : (z == 1) ? bk : bv;
    float*       out  = (z == 0) ? g_qh : (z == 1) ? g_kh : g_vh;
    const float scale = (z == 0) ? 0.17677669529663687f : 1.0f;  // 1/sqrt(32)

    const int tid  = threadIdx.x;
    const int wid  = tid >> 5;
    const int lane = tid & 31;
    const int g    = lane >> 2;   // groupID
    const int t    = lane & 3;    // thread-in-group
    const int wm   = wid >> 2;    // 0..1
    const int wn   = wid & 3;     // 0..3
    const int m0   = blockIdx.x * 128;
    const int n0   = blockIdx.y * 128;

    float acc[4][4][4];
    #pragma unroll
    for (int a = 0; a < 4; a++)
        #pragma unroll
        for (int b = 0; b < 4; b++)
            #pragma unroll
            for (int c = 0; c < 4; c++) acc[a][b][c] = 0.0f;

    for (int kt = 0; kt < 256; kt += 32) {
        #pragma unroll
        for (int i = 0; i < 4; i++) {
            int idx = tid + i * 256;          // 0..1023
            int row = idx >> 3;
            int c4  = (idx & 7) << 2;
            float4 xa = *(const float4*)&X[(size_t)(m0 + row) * 256 + kt + c4];
            Asu[row * 36 + c4 + 0] = f2tf(xa.x);
            Asu[row * 36 + c4 + 1] = f2tf(xa.y);
            Asu[row * 36 + c4 + 2] = f2tf(xa.z);
            Asu[row * 36 + c4 + 3] = f2tf(xa.w);
            float4 xb = *(const float4*)&Wt[(size_t)(n0 + row) * 256 + kt + c4];
            Bsu[row * 36 + c4 + 0] = f2tf(xb.x);
            Bsu[row * 36 + c4 + 1] = f2tf(xb.y);
            Bsu[row * 36 + c4 + 2] = f2tf(xb.z);
            Bsu[row * 36 + c4 + 3] = f2tf(xb.w);
        }
        __syncthreads();

        #pragma unroll
        for (int k8 = 0; k8 < 4; k8++) {
            const int k0 = k8 * 8;
            uint32_t bf[4][2];
            #pragma unroll
            for (int nt = 0; nt < 4; nt++) {
                int n = wn * 32 + nt * 8 + g;
                bf[nt][0] = Bsu[n * 36 + k0 + t];
                bf[nt][1] = Bsu[n * 36 + k0 + t + 4];
            }
            #pragma unroll
            for (int mt = 0; mt < 4; mt++) {
                int r = wm * 64 + mt * 16 + g;
                uint32_t af[4];
                af[0] = Asu[r * 36 + k0 + t];
                af[1] = Asu[(r + 8) * 36 + k0 + t];
                af[2] = Asu[r * 36 + k0 + t + 4];
                af[3] = Asu[(r + 8) * 36 + k0 + t + 4];
                #pragma unroll
                for (int nt = 0; nt < 4; nt++)
                    mma_tf32(acc[mt][nt], af, bf[nt]);
            }
        }
        __syncthreads();
    }

    // Epilogue: bias, scale, scatter
    #pragma unroll
    for (int mt = 0; mt < 4; mt++) {
        #pragma unroll
        for (int nt = 0; nt < 4; nt++) {
            int n  = n0 + wn * 32 + nt * 8 + 2 * t;
            int h  = n >> 5;
            int dk = n & 31;
            float b0 = bias[n], b1 = bias[n + 1];
            #pragma unroll
            for (int rs = 0; rs < 2; rs++) {
                int m   = m0 + wm * 64 + mt * 16 + g + 8 * rs;
                int blq = m >> 7;
                int ww  = m & 127;
                float2 val;
                val.x = (acc[mt][nt][2 * rs + 0] + b0) * scale;
                val.y = (acc[mt][nt][2 * rs + 1] + b1) * scale;
                *(float2*)&out[(((size_t)blq * 8 + h) * 128 + ww) * 32 + dk] = val;
            }
        }
    }
}

// ---------------------------------------------------------------------------
// Kernel B: attention per (b,l,h). S = QK^T (tf32 mma) -> softmax in regs ->
// write attn (fp32 from acc) -> P (tf32) -> O = PV (tf32 mma).
// 8 warps; warp w owns S rows 16w..16w+15 (all 128 cols).
// ---------------------------------------------------------------------------
#define QS_OFF 0
#define KS_OFF (128 * 36)
#define VT_OFF (KS_OFF + 128 * 36)
#define PS_OFF (VT_OFF + 32 * 133)
#define SMEM_B_WORDS (PS_OFF + 128 * 132)
#define SMEM_B_BYTES (SMEM_B_WORDS * 4)

__global__ __launch_bounds__(256) void attn_kernel(float* __restrict__ attn_out)
{
    extern __shared__ uint32_t smu[];
    uint32_t* Qs = smu + QS_OFF;   // [w][dk] stride 36
    uint32_t* Ks = smu + KS_OFF;   // [w][dk] stride 36
    uint32_t* Vt = smu + VT_OFF;   // [dk][j] stride 133
    uint32_t* Ps = smu + PS_OFF;   // [i][j]  stride 132 (tf32)

    const int blk  = blockIdx.x;
    const int tid  = threadIdx.x;
    const int wid  = tid >> 5;
    const int lane = tid & 31;
    const int g    = lane >> 2;
    const int t    = lane & 3;

    const float4* Qg = (const float4*)(g_qh + (size_t)blk * 4096);
    const float4* Kg = (const float4*)(g_kh + (size_t)blk * 4096);
    const float4* Vg = (const float4*)(g_vh + (size_t)blk * 4096);

    #pragma unroll
    for (int i = 0; i < 4; i++) {
        int idx = tid + i * 256;       // 0..1023
        int row = idx >> 3;
        int c4  = (idx & 7) << 2;
        float4 xq = Qg[idx];
        Qs[row * 36 + c4 + 0] = f2tf(xq.x);
        Qs[row * 36 + c4 + 1] = f2tf(xq.y);
        Qs[row * 36 + c4 + 2] = f2tf(xq.z);
        Qs[row * 36 + c4 + 3] = f2tf(xq.w);
        float4 xk = Kg[idx];
        Ks[row * 36 + c4 + 0] = f2tf(xk.x);
        Ks[row * 36 + c4 + 1] = f2tf(xk.y);
        Ks[row * 36 + c4 + 2] = f2tf(xk.z);
        Ks[row * 36 + c4 + 3] = f2tf(xk.w);
        float4 xv = Vg[idx];           // V[j=row][d=c4..c4+3] -> Vt[d][j]
        Vt[(c4 + 0) * 133 + row] = f2tf(xv.x);
        Vt[(c4 + 1) * 133 + row] = f2tf(xv.y);
        Vt[(c4 + 2) * 133 + row] = f2tf(xv.z);
        Vt[(c4 + 3) * 133 + row] = f2tf(xv.w);
    }
    __syncthreads();

    // S = Q K^T : 16 rows x 128 cols per warp
    float sacc[16][4];
    #pragma unroll
    for (int nt = 0; nt < 16; nt++)
        #pragma unroll
        for (int c = 0; c < 4; c++) sacc[nt][c] = 0.0f;

    const int rbase = wid * 16 + g;
    #pragma unroll
    for (int k8 = 0; k8 < 4; k8++) {
        const int k0 = k8 * 8;
        uint32_t af[4];
        af[0] = Qs[rbase * 36 + k0 + t];
        af[1] = Qs[(rbase + 8) * 36 + k0 + t];
        af[2] = Qs[rbase * 36 + k0 + t + 4];
        af[3] = Qs[(rbase + 8) * 36 + k0 + t + 4];
        #pragma unroll
        for (int nt = 0; nt < 16; nt++) {
            int n = nt * 8 + g;
            uint32_t bf[2];
            bf[0] = Ks[n * 36 + k0 + t];
            bf[1] = Ks[n * 36 + k0 + t + 4];
            mma_tf32(sacc[nt], af, bf);
        }
    }

    // Softmax per row set (rs=0: regs 0,1 ; rs=1: regs 2,3). Lanes in a quad
    // (xor 1, xor 2) share the row.
    float inv[2];
    #pragma unroll
    for (int rs = 0; rs < 2; rs++) {
        float mx = -1e30f;
        #pragma unroll
        for (int nt = 0; nt < 16; nt++) {
            mx = fmaxf(mx, sacc[nt][2 * rs]);
            mx = fmaxf(mx, sacc[nt][2 * rs + 1]);
        }
        mx = fmaxf(mx, __shfl_xor_sync(0xffffffffu, mx, 1));
        mx = fmaxf(mx, __shfl_xor_sync(0xffffffffu, mx, 2));
        float s = 0.0f;
        #pragma unroll
        for (int nt = 0; nt < 16; nt++) {
            float e0 = __expf(sacc[nt][2 * rs] - mx);
            float e1 = __expf(sacc[nt][2 * rs + 1] - mx);
            sacc[nt][2 * rs] = e0; sacc[nt][2 * rs + 1] = e1;
            s += e0 + e1;
        }
        s += __shfl_xor_sync(0xffffffffu, s, 1);
        s += __shfl_xor_sync(0xffffffffu, s, 2);
        inv[rs] = 1.0f / s;
    }

    // Write attn (fp32) + Ps (tf32)
    const size_t abase = (size_t)blk * 16384;
    #pragma unroll
    for (int nt = 0; nt < 16; nt++) {
        int col = nt * 8 + 2 * t;
        #pragma unroll
        for (int rs = 0; rs < 2; rs++) {
            int row = rbase + 8 * rs;
            float p0 = sacc[nt][2 * rs] * inv[rs];
            float p1 = sacc[nt][2 * rs + 1] * inv[rs];
            float2 pv; pv.x = p0; pv.y = p1;
            *(float2*)&attn_out[abase + (size_t)row * 128 + col] = pv;
            Ps[row * 132 + col]     = f2tf(p0);
            Ps[row * 132 + col + 1] = f2tf(p1);
        }
    }
    __syncthreads();

    // O = P V : 16 rows x 32 cols per warp
    float oacc[4][4];
    #pragma unroll
    for (int nt = 0; nt < 4; nt++)
        #pragma unroll
        for (int c = 0; c < 4; c++) oacc[nt][c] = 0.0f;

    #pragma unroll
    for (int ks = 0; ks < 16; ks++) {
        const int k0 = ks * 8;
        uint32_t af[4];
        af[0] = Ps[rbase * 132 + k0 + t];
        af[1] = Ps[(rbase + 8) * 132 + k0 + t];
        af[2] = Ps[rbase * 132 + k0 + t + 4];
        af[3] = Ps[(rbase + 8) * 132 + k0 + t + 4];
        #pragma unroll
        for (int nt = 0; nt < 4; nt++) {
            int d = nt * 8 + g;
            uint32_t bf[2];
            bf[0] = Vt[d * 133 + k0 + t];
            bf[1] = Vt[d * 133 + k0 + t + 4];
            mma_tf32(oacc[nt], af, bf);
        }
    }

    // Store O to [m][d] layout
    const int blq = blk >> 3;
    const int h   = blk & 7;
    #pragma unroll
    for (int nt = 0; nt < 4; nt++) {
        int col = h * 32 + nt * 8 + 2 * t;
        #pragma unroll
        for (int rs = 0; rs < 2; rs++) {
            int m = blq * 128 + rbase + 8 * rs;
            float2 val; val.x = oacc[nt][2 * rs]; val.y = oacc[nt][2 * rs + 1];
            *(float2*)&g_attnout[(size_t)m * 256 + col] = val;
        }
    }
}

// ---------------------------------------------------------------------------
// Kernel C: FC + residual + LayerNorm, fused. Block tile 128x256 (full row),
// 512 threads = 16 warps (4x4), warp tile 32x64.
// ---------------------------------------------------------------------------
#define C_AS_OFF 0
#define C_BS_OFF (128 * 36)
#define C_RED_OFF (C_BS_OFF + 256 * 36)
#define SMEM_C_WORDS (C_RED_OFF + 128 * 8)
#define SMEM_C_BYTES (SMEM_C_WORDS * 4)

__global__ __launch_bounds__(512) void fc_ln_kernel(
    const float* __restrict__ Wfc, const float* __restrict__ bfc,
    const float* __restrict__ resid,
    const float* __restrict__ ln_w, const float* __restrict__ ln_b,
    float* __restrict__ out)
{
    extern __shared__ uint32_t smu[];
    uint32_t* Asu = smu + C_AS_OFF;            // [128][36]
    uint32_t* Bsu = smu + C_BS_OFF;            // [256][36]
    float*    red = (float*)(smu + C_RED_OFF); // [128][8]: sum[0..3], sq[4..7]

    const int tid  = threadIdx.x;
    const int wid  = tid >> 5;
    const int lane = tid & 31;
    const int g    = lane >> 2;
    const int t    = lane & 3;
    const int wm   = wid >> 2;   // 0..3
    const int wn   = wid & 3;    // 0..3
    const int m0   = blockIdx.x * 128;

    float acc[2][8][4];
    #pragma unroll
    for (int a = 0; a < 2; a++)
        #pragma unroll
        for (int b = 0; b < 8; b++)
            #pragma unroll
            for (int c = 0; c < 4; c++) acc[a][b][c] = 0.0f;

    for (int kt = 0; kt < 256; kt += 32) {
        #pragma unroll
        for (int i = 0; i < 2; i++) {
            int idx = tid + i * 512;    // A: 1024 float4
            int row = idx >> 3;
            int c4  = (idx & 7) << 2;
            float4 xa = *(const float4*)&g_attnout[(size_t)(m0 + row) * 256 + kt + c4];
            Asu[row * 36 + c4 + 0] = f2tf(xa.x);
            Asu[row * 36 + c4 + 1] = f2tf(xa.y);
            Asu[row * 36 + c4 + 2] = f2tf(xa.z);
            Asu[row * 36 + c4 + 3] = f2tf(xa.w);
        }
        #pragma unroll
        for (int i = 0; i < 4; i++) {
            int idx = tid + i * 512;    // B: 2048 float4
            int row = idx >> 3;         // 0..255
            int c4  = (idx & 7) << 2;
            float4 xb = *(const float4*)&Wfc[(size_t)row * 256 + kt + c4];
            Bsu[row * 36 + c4 + 0] = f2tf(xb.x);
            Bsu[row * 36 + c4 + 1] = f2tf(xb.y);
            Bsu[row * 36 + c4 + 2] = f2tf(xb.z);
            Bsu[row * 36 + c4 + 3] = f2tf(xb.w);
        }
        __syncthreads();

        #pragma unroll
        for (int k8 = 0; k8 < 4; k8++) {
            const int k0 = k8 * 8;
            uint32_t af[2][4];
            #pragma unroll
            for (int mt = 0; mt < 2; mt++) {
                int r = wm * 32 + mt * 16 + g;
                af[mt][0] = Asu[r * 36 + k0 + t];
                af[mt][1] = Asu[(r + 8) * 36 + k0 + t];
                af[mt][2] = Asu[r * 36 + k0 + t + 4];
                af[mt][3] = Asu[(r + 8) * 36 + k0 + t + 4];
            }
            #pragma unroll
            for (int nt = 0; nt < 8; nt++) {
                int n = wn * 64 + nt * 8 + g;
                uint32_t bf[2];
                bf[0] = Bsu[n * 36 + k0 + t];
                bf[1] = Bsu[n * 36 + k0 + t + 4];
                #pragma unroll
                for (int mt = 0; mt < 2; mt++)
                    mma_tf32(acc[mt][nt], af[mt], bf);
            }
        }
        __syncthreads();
    }

    // Add bias + residual, accumulate row statistics
    #pragma unroll
    for (int mt = 0; mt < 2; mt++) {
        #pragma unroll
        for (int rs = 0; rs < 2; rs++) {
            int rloc = wm * 32 + mt * 16 + g + 8 * rs;
            float s = 0.0f, sq = 0.0f;
            #pragma unroll
            for (int nt = 0; nt < 8; nt++) {
                int col = wn * 64 + nt * 8 + 2 * t;
                float2 rr = *(const float2*)&resid[(size_t)(m0 + rloc) * 256 + col];
                float v0 = acc[mt][nt][2 * rs]     + bfc[col]     + rr.x;
                float v1 = acc[mt][nt][2 * rs + 1] + bfc[col + 1] + rr.y;
                acc[mt][nt][2 * rs]     = v0;
                acc[mt][nt][2 * rs + 1] = v1;
                s  += v0 + v1;
                sq += v0 * v0 + v1 * v1;
            }
            s  += __shfl_xor_sync(0xffffffffu, s, 1);
            s  += __shfl_xor_sync(0xffffffffu, s, 2);
            sq += __shfl_xor_sync(0xffffffffu, sq, 1);
            sq += __shfl_xor_sync(0xffffffffu, sq, 2);
            if (t == 0) {
                red[rloc * 8 + wn]     = s;
                red[rloc * 8 + 4 + wn] = sq;
            }
        }
    }
    __syncthreads();

    // Normalize + write
    #pragma unroll
    for (int mt = 0; mt < 2; mt++) {
        #pragma unroll
        for (int rs = 0; rs < 2; rs++) {
            int rloc = wm * 32 + mt * 16 + g + 8 * rs;
            float s  = red[rloc * 8 + 0] + red[rloc * 8 + 1] + red[rloc * 8 + 2] + red[rloc * 8 + 3];
            float sq = red[rloc * 8 + 4] + red[rloc * 8 + 5] + red[rloc * 8 + 6] + red[rloc * 8 + 7];
            float mu   = s * (1.0f / 256.0f);
            float var  = sq * (1.0f / 256.0f) - mu * mu;
            float rstd = rsqrtf(var + 1e-6f);
            #pragma unroll
            for (int nt = 0; nt < 8; nt++) {
                int col = wn * 64 + nt * 8 + 2 * t;
                float2 lw = *(const float2*)&ln_w[col];
                float2 lb = *(const float2*)&ln_b[col];
                float2 o;
                o.x = (acc[mt][nt][2 * rs]     - mu) * rstd * lw.x + lb.x;
                o.y = (acc[mt][nt][2 * rs + 1] - mu) * rstd * lw.y + lb.y;
                *(float2*)&out[(size_t)(m0 + rloc) * 256 + col] = o;
            }
        }
    }
}

// ---------------------------------------------------------------------------
extern "C" void kernel_launch(void* const* d_in, const int* in_sizes, int n_in,
                              void* d_out, int out_size)
{
    const float* q    = (const float*)d_in[0];
    const float* k    = (const float*)d_in[1];
    const float* v    = (const float*)d_in[2];
    const float* Wq   = (const float*)d_in[3];
    const float* bq   = (const float*)d_in[4];
    const float* Wk   = (const float*)d_in[5];
    const float* bk   = (const float*)d_in[6];
    const float* Wv   = (const float*)d_in[7];
    const float* bv   = (const float*)d_in[8];
    const float* Wfc  = (const float*)d_in[9];
    const float* bfc  = (const float*)d_in[10];
    const float* ln_w = (const float*)d_in[11];
    const float* ln_b = (const float*)d_in[12];

    float* out  = (float*)d_out;
    float* attn = out + OUT_ELEMS;

    static bool attr_set = false;
    if (!attr_set) {
        cudaFuncSetAttribute(attn_kernel,  cudaFuncAttributeMaxDynamicSharedMemorySize, SMEM_B_BYTES);
        cudaFuncSetAttribute(fc_ln_kernel, cudaFuncAttributeMaxDynamicSharedMemorySize, SMEM_C_BYTES);
        attr_set = true;
    }

    gemm_proj<<<dim3(512, 2, 3), 256>>>(q, k, v, Wq, Wk, Wv, bq, bk, bv);
    attn_kernel<<<NBLH, 256, SMEM_B_BYTES>>>(attn);
    fc_ln_kernel<<<512, 512, SMEM_C_BYTES>>>(Wfc, bfc, q, ln_w, ln_b, out);
}

// round 3
// speedup vs baseline: 2.9917x; 1.2165x over previous
#include <cuda_runtime.h>
#include <math.h>
#include <stdint.h>

#define B_    4
#define L_    128
#define W_    128
#define D_    256
#define H_    8
#define DK_   32
#define MROWS (B_*L_*W_)
#define NBLH  (B_*L_*H_)
#define OUT_ELEMS ((size_t)MROWS * D_)

// Scratch (tf32 bit patterns stored in float arrays)
__device__ float g_qh[(size_t)NBLH * W_ * DK_];
__device__ float g_kh[(size_t)NBLH * W_ * DK_];
__device__ float g_vh[(size_t)NBLH * W_ * DK_];
__device__ float g_attnout[OUT_ELEMS];
__device__ uint32_t g_wtf[4 * 65536];   // Wq, Wk, Wv, Wfc pre-converted to tf32

// ---------------------------------------------------------------------------
__device__ __forceinline__ uint32_t f2tf(float x) {
    uint32_t r;
    asm("cvt.rna.tf32.f32 %0, %1;" : "=r"(r) : "f"(x));
    return r;
}
__device__ __forceinline__ void mma_tf32(float* d, const uint32_t* a, const uint32_t* b) {
    asm volatile(
        "mma.sync.aligned.m16n8k8.row.col.f32.tf32.tf32.f32 "
        "{%0,%1,%2,%3}, {%4,%5,%6,%7}, {%8,%9}, {%0,%1,%2,%3};"
        : "+f"(d[0]), "+f"(d[1]), "+f"(d[2]), "+f"(d[3])
        : "r"(a[0]), "r"(a[1]), "r"(a[2]), "r"(a[3]), "r"(b[0]), "r"(b[1]));
}
__device__ __forceinline__ uint32_t smem_u32(const void* p) {
    uint32_t a;
    asm("{ .reg .u64 t; cvta.to.shared.u64 t, %1; cvt.u32.u64 %0, t; }" : "=r"(a) : "l"(p));
    return a;
}
__device__ __forceinline__ void cp16(uint32_t dst, const void* src) {
    asm volatile("cp.async.cg.shared.global [%0], [%1], 16;" :: "r"(dst), "l"(src));
}
#define CP_COMMIT() asm volatile("cp.async.commit_group;")
#define CP_WAIT(n)  asm volatile("cp.async.wait_group %0;" :: "n"(n))

// ---------------------------------------------------------------------------
// Weight pre-conversion to tf32
// ---------------------------------------------------------------------------
__global__ void wconv(const float* __restrict__ Wq, const float* __restrict__ Wk,
                      const float* __restrict__ Wv, const float* __restrict__ Wfc)
{
    int i = blockIdx.x * 256 + threadIdx.x;   // 65536 threads
    g_wtf[i]          = f2tf(Wq[i]);
    g_wtf[65536 + i]  = f2tf(Wk[i]);
    g_wtf[131072 + i] = f2tf(Wv[i]);
    g_wtf[196608 + i] = f2tf(Wfc[i]);
}

// ---------------------------------------------------------------------------
// Kernel A: QKV projection, cp.async double-buffered.
// Block 128x128, 8 warps (2x4), warp tile 64x32, BK=32.
// Outputs tf32 bit patterns into g_qh/g_kh/g_vh (Q pre-scaled).
// ---------------------------------------------------------------------------
#define GP_SMEM_BYTES (2 * 4608 * 2 * 4)    // 73728

__global__ __launch_bounds__(256, 2) void gemm_proj(
    const float* __restrict__ q, const float* __restrict__ k, const float* __restrict__ v,
    const float* __restrict__ bq, const float* __restrict__ bk, const float* __restrict__ bv)
{
    extern __shared__ uint32_t sm[];
    uint32_t* As = sm;               // [2][128*36]
    uint32_t* Bs = sm + 2 * 4608;    // [2][128*36]

    const int z = blockIdx.z;
    const float*    X    = (z == 0) ? q : (z == 1) ? k : v;
    const uint32_t* Wtf  = g_wtf + (size_t)z * 65536;
    const float*    bias = (z == 0) ? bq : (z == 1) ? bk : bv;
    float*          out  = (z == 0) ? g_qh : (z == 1) ? g_kh : g_vh;
    const float scale = (z == 0) ? 0.17677669529663687f : 1.0f;

    const int tid  = threadIdx.x;
    const int wid  = tid >> 5;
    const int lane = tid & 31;
    const int g    = lane >> 2;
    const int t    = lane & 3;
    const int wm   = wid >> 2;
    const int wn   = wid & 3;
    const int m0   = blockIdx.x * 128;
    const int n0   = blockIdx.y * 128;

    const uint32_t as_b = smem_u32(As);
    const uint32_t bs_b = smem_u32(Bs);

    // prologue: stage 0
    {
        #pragma unroll
        for (int i = 0; i < 4; i++) {
            int idx = tid + i * 256; int row = idx >> 3; int c4 = (idx & 7) << 2;
            cp16(as_b + (uint32_t)(row * 36 + c4) * 4, &X[(size_t)(m0 + row) * 256 + c4]);
            cp16(bs_b + (uint32_t)(row * 36 + c4) * 4, &Wtf[(size_t)(n0 + row) * 256 + c4]);
        }
        CP_COMMIT();
    }

    float acc[4][4][4];
    #pragma unroll
    for (int a = 0; a < 4; a++)
        #pragma unroll
        for (int b = 0; b < 4; b++)
            #pragma unroll
            for (int c = 0; c < 4; c++) acc[a][b][c] = 0.0f;

    for (int kt8 = 0; kt8 < 8; kt8++) {
        if (kt8 < 7) {
            int s  = (kt8 + 1) & 1;
            int kt = (kt8 + 1) * 32;
            #pragma unroll
            for (int i = 0; i < 4; i++) {
                int idx = tid + i * 256; int row = idx >> 3; int c4 = (idx & 7) << 2;
                cp16(as_b + (uint32_t)(s * 4608 + row * 36 + c4) * 4, &X[(size_t)(m0 + row) * 256 + kt + c4]);
                cp16(bs_b + (uint32_t)(s * 4608 + row * 36 + c4) * 4, &Wtf[(size_t)(n0 + row) * 256 + kt + c4]);
            }
            CP_COMMIT();
            CP_WAIT(1);
        } else {
            CP_WAIT(0);
        }
        __syncthreads();

        const uint32_t* Ac = As + (kt8 & 1) * 4608;
        const uint32_t* Bc = Bs + (kt8 & 1) * 4608;

        #pragma unroll
        for (int k8 = 0; k8 < 4; k8++) {
            const int k0 = k8 * 8;
            uint32_t bf[4][2];
            #pragma unroll
            for (int nt = 0; nt < 4; nt++) {
                int n = wn * 32 + nt * 8 + g;
                bf[nt][0] = Bc[n * 36 + k0 + t];
                bf[nt][1] = Bc[n * 36 + k0 + t + 4];
            }
            #pragma unroll
            for (int mt = 0; mt < 4; mt++) {
                int r = wm * 64 + mt * 16 + g;
                uint32_t af[4];
                af[0] = f2tf(__uint_as_float(Ac[r * 36 + k0 + t]));
                af[1] = f2tf(__uint_as_float(Ac[(r + 8) * 36 + k0 + t]));
                af[2] = f2tf(__uint_as_float(Ac[r * 36 + k0 + t + 4]));
                af[3] = f2tf(__uint_as_float(Ac[(r + 8) * 36 + k0 + t + 4]));
                #pragma unroll
                for (int nt = 0; nt < 4; nt++)
                    mma_tf32(acc[mt][nt], af, bf[nt]);
            }
        }
        __syncthreads();
    }

    // epilogue: bias, scale, convert to tf32 bits, scatter to [blq][h][w][dk]
    #pragma unroll
    for (int mt = 0; mt < 4; mt++) {
        #pragma unroll
        for (int nt = 0; nt < 4; nt++) {
            int n  = n0 + wn * 32 + nt * 8 + 2 * t;
            int h  = n >> 5;
            int dk = n & 31;
            float b0 = bias[n], b1 = bias[n + 1];
            #pragma unroll
            for (int rs = 0; rs < 2; rs++) {
                int m   = m0 + wm * 64 + mt * 16 + g + 8 * rs;
                int blq = m >> 7;
                int ww  = m & 127;
                uint2 val;
                val.x = f2tf((acc[mt][nt][2 * rs + 0] + b0) * scale);
                val.y = f2tf((acc[mt][nt][2 * rs + 1] + b1) * scale);
                *(uint2*)&out[(((size_t)blq * 8 + h) * 128 + ww) * 32 + dk] = val;
            }
        }
    }
}

// ---------------------------------------------------------------------------
// Kernel B: attention per (b,l,h). S = QK^T -> softmax in regs -> attn write
// (fp32) -> PV via register-shuffle transposed A-fragments (no Ps smem).
// smem: Qs[128*36] + Ks[128*36] + Vt[32*133] = 53888 B -> 2 CTAs/SM.
// ---------------------------------------------------------------------------
#define ATTN_SMEM_BYTES ((4608 + 4608 + 4256) * 4)

__global__ __launch_bounds__(256, 2) void attn_kernel(float* __restrict__ attn_out)
{
    extern __shared__ uint32_t smu[];
    uint32_t* Qs = smu;            // [w][dk] stride 36 (tf32 bits)
    uint32_t* Ks = smu + 4608;
    uint32_t* Vt = smu + 9216;     // [dk][j] stride 133 (tf32 bits)

    const int blk  = blockIdx.x;
    const int tid  = threadIdx.x;
    const int wid  = tid >> 5;
    const int lane = tid & 31;
    const int g    = lane >> 2;
    const int t    = lane & 3;

    const uint4* Qg = (const uint4*)(g_qh + (size_t)blk * 4096);
    const uint4* Kg = (const uint4*)(g_kh + (size_t)blk * 4096);
    const uint4* Vg = (const uint4*)(g_vh + (size_t)blk * 4096);

    #pragma unroll
    for (int i = 0; i < 4; i++) {
        int idx = tid + i * 256;
        int row = idx >> 3;
        int c4  = (idx & 7) << 2;
        uint4 xq = Qg[idx];
        Qs[row * 36 + c4 + 0] = xq.x; Qs[row * 36 + c4 + 1] = xq.y;
        Qs[row * 36 + c4 + 2] = xq.z; Qs[row * 36 + c4 + 3] = xq.w;
        uint4 xk = Kg[idx];
        Ks[row * 36 + c4 + 0] = xk.x; Ks[row * 36 + c4 + 1] = xk.y;
        Ks[row * 36 + c4 + 2] = xk.z; Ks[row * 36 + c4 + 3] = xk.w;
        uint4 xv = Vg[idx];
        Vt[(c4 + 0) * 133 + row] = xv.x; Vt[(c4 + 1) * 133 + row] = xv.y;
        Vt[(c4 + 2) * 133 + row] = xv.z; Vt[(c4 + 3) * 133 + row] = xv.w;
    }
    __syncthreads();

    // S = Q K^T : 16 rows x 128 cols per warp
    float sacc[16][4];
    #pragma unroll
    for (int nt = 0; nt < 16; nt++)
        #pragma unroll
        for (int c = 0; c < 4; c++) sacc[nt][c] = 0.0f;

    const int rbase = wid * 16 + g;
    #pragma unroll
    for (int k8 = 0; k8 < 4; k8++) {
        const int k0 = k8 * 8;
        uint32_t af[4];
        af[0] = Qs[rbase * 36 + k0 + t];
        af[1] = Qs[(rbase + 8) * 36 + k0 + t];
        af[2] = Qs[rbase * 36 + k0 + t + 4];
        af[3] = Qs[(rbase + 8) * 36 + k0 + t + 4];
        #pragma unroll
        for (int nt = 0; nt < 16; nt++) {
            int n = nt * 8 + g;
            uint32_t bf[2];
            bf[0] = Ks[n * 36 + k0 + t];
            bf[1] = Ks[n * 36 + k0 + t + 4];
            mma_tf32(sacc[nt], af, bf);
        }
    }

    // softmax (rows shared by lane quads via xor 1,2)
    float inv[2];
    #pragma unroll
    for (int rs = 0; rs < 2; rs++) {
        float mx = -1e30f;
        #pragma unroll
        for (int nt = 0; nt < 16; nt++) {
            mx = fmaxf(mx, sacc[nt][2 * rs]);
            mx = fmaxf(mx, sacc[nt][2 * rs + 1]);
        }
        mx = fmaxf(mx, __shfl_xor_sync(0xffffffffu, mx, 1));
        mx = fmaxf(mx, __shfl_xor_sync(0xffffffffu, mx, 2));
        float s = 0.0f;
        #pragma unroll
        for (int nt = 0; nt < 16; nt++) {
            float e0 = __expf(sacc[nt][2 * rs] - mx);
            float e1 = __expf(sacc[nt][2 * rs + 1] - mx);
            sacc[nt][2 * rs] = e0; sacc[nt][2 * rs + 1] = e1;
            s += e0 + e1;
        }
        s += __shfl_xor_sync(0xffffffffu, s, 1);
        s += __shfl_xor_sync(0xffffffffu, s, 2);
        inv[rs] = 1.0f / s;
    }

    // normalize in place, write attn (fp32)
    #pragma unroll
    for (int nt = 0; nt < 16; nt++) {
        sacc[nt][0] *= inv[0]; sacc[nt][1] *= inv[0];
        sacc[nt][2] *= inv[1]; sacc[nt][3] *= inv[1];
    }
    const size_t abase = (size_t)blk * 16384;
    #pragma unroll
    for (int nt = 0; nt < 16; nt++) {
        int col = nt * 8 + 2 * t;
        float2 p0; p0.x = sacc[nt][0]; p0.y = sacc[nt][1];
        float2 p1; p1.x = sacc[nt][2]; p1.y = sacc[nt][3];
        *(float2*)&attn_out[abase + (size_t)rbase * 128 + col]       = p0;
        *(float2*)&attn_out[abase + (size_t)(rbase + 8) * 128 + col] = p1;
    }

    // O = P V via shuffle-transposed A fragments
    float oacc[4][4];
    #pragma unroll
    for (int nt = 0; nt < 4; nt++)
        #pragma unroll
        for (int c = 0; c < 4; c++) oacc[nt][c] = 0.0f;

    const int src0 = (lane & 28) | ((lane & 3) >> 1);
    const int src2 = src0 + 2;
    const bool sel = lane & 1;

    #pragma unroll
    for (int ks = 0; ks < 16; ks++) {
        float s00 = __shfl_sync(0xffffffffu, sacc[ks][0], src0);
        float s01 = __shfl_sync(0xffffffffu, sacc[ks][1], src0);
        float s02 = __shfl_sync(0xffffffffu, sacc[ks][2], src0);
        float s03 = __shfl_sync(0xffffffffu, sacc[ks][3], src0);
        float s20 = __shfl_sync(0xffffffffu, sacc[ks][0], src2);
        float s21 = __shfl_sync(0xffffffffu, sacc[ks][1], src2);
        float s22 = __shfl_sync(0xffffffffu, sacc[ks][2], src2);
        float s23 = __shfl_sync(0xffffffffu, sacc[ks][3], src2);
        uint32_t af[4];
        af[0] = f2tf(sel ? s01 : s00);
        af[1] = f2tf(sel ? s03 : s02);
        af[2] = f2tf(sel ? s21 : s20);
        af[3] = f2tf(sel ? s23 : s22);
        const int k0 = ks * 8;
        #pragma unroll
        for (int nt = 0; nt < 4; nt++) {
            int d = nt * 8 + g;
            uint32_t bf[2];
            bf[0] = Vt[d * 133 + k0 + t];
            bf[1] = Vt[d * 133 + k0 + t + 4];
            mma_tf32(oacc[nt], af, bf);
        }
    }

    // store O as tf32 bits to [m][d]
    const int blq = blk >> 3;
    const int h   = blk & 7;
    #pragma unroll
    for (int nt = 0; nt < 4; nt++) {
        int col = h * 32 + nt * 8 + 2 * t;
        #pragma unroll
        for (int rs = 0; rs < 2; rs++) {
            int m = blq * 128 + rbase + 8 * rs;
            uint2 val;
            val.x = f2tf(oacc[nt][2 * rs]);
            val.y = f2tf(oacc[nt][2 * rs + 1]);
            *(uint2*)&g_attnout[(size_t)m * 256 + col] = val;
        }
    }
}

// ---------------------------------------------------------------------------
// Kernel C: FC + residual + LayerNorm, cp.async double-buffered.
// Block 128x256, 512 threads (16 warps, 4x4), warp tile 32x64.
// A (attnout) and B (Wfc) are already tf32 bits -> zero cvt in mainloop.
// ---------------------------------------------------------------------------
#define FC_AS_W   (2 * 4608)
#define FC_BS_W   (2 * 9216)
#define FC_SMEM_BYTES ((FC_AS_W + FC_BS_W + 1024) * 4)   // 114688

__global__ __launch_bounds__(512, 1) void fc_ln_kernel(
    const float* __restrict__ bfc, const float* __restrict__ resid,
    const float* __restrict__ ln_w, const float* __restrict__ ln_b,
    float* __restrict__ out)
{
    extern __shared__ uint32_t smu[];
    uint32_t* As  = smu;                         // [2][128*36]
    uint32_t* Bs  = smu + FC_AS_W;               // [2][256*36]
    float*    red = (float*)(smu + FC_AS_W + FC_BS_W);   // [128][8]

    const uint32_t* Wtf = g_wtf + 196608;
    const int tid  = threadIdx.x;
    const int wid  = tid >> 5;
    const int lane = tid & 31;
    const int g    = lane >> 2;
    const int t    = lane & 3;
    const int wm   = wid >> 2;
    const int wn   = wid & 3;
    const int m0   = blockIdx.x * 128;

    const uint32_t as_b = smem_u32(As);
    const uint32_t bs_b = smem_u32(Bs);

    {
        #pragma unroll
        for (int i = 0; i < 2; i++) {
            int idx = tid + i * 512; int row = idx >> 3; int c4 = (idx & 7) << 2;
            cp16(as_b + (uint32_t)(row * 36 + c4) * 4, &g_attnout[(size_t)(m0 + row) * 256 + c4]);
        }
        #pragma unroll
        for (int i = 0; i < 4; i++) {
            int idx = tid + i * 512; int row = idx >> 3; int c4 = (idx & 7) << 2;
            cp16(bs_b + (uint32_t)(row * 36 + c4) * 4, &Wtf[(size_t)row * 256 + c4]);
        }
        CP_COMMIT();
    }

    float acc[2][8][4];
    #pragma unroll
    for (int a = 0; a < 2; a++)
        #pragma unroll
        for (int b = 0; b < 8; b++)
            #pragma unroll
            for (int c = 0; c < 4; c++) acc[a][b][c] = 0.0f;

    for (int kt8 = 0; kt8 < 8; kt8++) {
        if (kt8 < 7) {
            int s  = (kt8 + 1) & 1;
            int kt = (kt8 + 1) * 32;
            #pragma unroll
            for (int i = 0; i < 2; i++) {
                int idx = tid + i * 512; int row = idx >> 3; int c4 = (idx & 7) << 2;
                cp16(as_b + (uint32_t)(s * 4608 + row * 36 + c4) * 4,
                     &g_attnout[(size_t)(m0 + row) * 256 + kt + c4]);
            }
            #pragma unroll
            for (int i = 0; i < 4; i++) {
                int idx = tid + i * 512; int row = idx >> 3; int c4 = (idx & 7) << 2;
                cp16(bs_b + (uint32_t)(s * 9216 + row * 36 + c4) * 4,
                     &Wtf[(size_t)row * 256 + kt + c4]);
            }
            CP_COMMIT();
            CP_WAIT(1);
        } else {
            CP_WAIT(0);
        }
        __syncthreads();

        const uint32_t* Ac = As + (kt8 & 1) * 4608;
        const uint32_t* Bc = Bs + (kt8 & 1) * 9216;

        #pragma unroll
        for (int k8 = 0; k8 < 4; k8++) {
            const int k0 = k8 * 8;
            uint32_t af[2][4];
            #pragma unroll
            for (int mt = 0; mt < 2; mt++) {
                int r = wm * 32 + mt * 16 + g;
                af[mt][0] = Ac[r * 36 + k0 + t];
                af[mt][1] = Ac[(r + 8) * 36 + k0 + t];
                af[mt][2] = Ac[r * 36 + k0 + t + 4];
                af[mt][3] = Ac[(r + 8) * 36 + k0 + t + 4];
            }
            #pragma unroll
            for (int nt = 0; nt < 8; nt++) {
                int n = wn * 64 + nt * 8 + g;
                uint32_t bf[2];
                bf[0] = Bc[n * 36 + k0 + t];
                bf[1] = Bc[n * 36 + k0 + t + 4];
                #pragma unroll
                for (int mt = 0; mt < 2; mt++)
                    mma_tf32(acc[mt][nt], af[mt], bf);
            }
        }
        __syncthreads();
    }

    // bias + residual + row stats
    #pragma unroll
    for (int mt = 0; mt < 2; mt++) {
        #pragma unroll
        for (int rs = 0; rs < 2; rs++) {
            int rloc = wm * 32 + mt * 16 + g + 8 * rs;
            float s = 0.0f, sq = 0.0f;
            #pragma unroll
            for (int nt = 0; nt < 8; nt++) {
                int col = wn * 64 + nt * 8 + 2 * t;
                float2 rr = *(const float2*)&resid[(size_t)(m0 + rloc) * 256 + col];
                float v0 = acc[mt][nt][2 * rs]     + bfc[col]     + rr.x;
                float v1 = acc[mt][nt][2 * rs + 1] + bfc[col + 1] + rr.y;
                acc[mt][nt][2 * rs]     = v0;
                acc[mt][nt][2 * rs + 1] = v1;
                s  += v0 + v1;
                sq += v0 * v0 + v1 * v1;
            }
            s  += __shfl_xor_sync(0xffffffffu, s, 1);
            s  += __shfl_xor_sync(0xffffffffu, s, 2);
            sq += __shfl_xor_sync(0xffffffffu, sq, 1);
            sq += __shfl_xor_sync(0xffffffffu, sq, 2);
            if (t == 0) {
                red[rloc * 8 + wn]     = s;
                red[rloc * 8 + 4 + wn] = sq;
            }
        }
    }
    __syncthreads();

    #pragma unroll
    for (int mt = 0; mt < 2; mt++) {
        #pragma unroll
        for (int rs = 0; rs < 2; rs++) {
            int rloc = wm * 32 + mt * 16 + g + 8 * rs;
            float s  = red[rloc * 8 + 0] + red[rloc * 8 + 1] + red[rloc * 8 + 2] + red[rloc * 8 + 3];
            float sq = red[rloc * 8 + 4] + red[rloc * 8 + 5] + red[rloc * 8 + 6] + red[rloc * 8 + 7];
            float mu   = s * (1.0f / 256.0f);
            float var  = sq * (1.0f / 256.0f) - mu * mu;
            float rstd = rsqrtf(var + 1e-6f);
            #pragma unroll
            for (int nt = 0; nt < 8; nt++) {
                int col = wn * 64 + nt * 8 + 2 * t;
                float2 lw = *(const float2*)&ln_w[col];
                float2 lb = *(const float2*)&ln_b[col];
                float2 o;
                o.x = (acc[mt][nt][2 * rs]     - mu) * rstd * lw.x + lb.x;
                o.y = (acc[mt][nt][2 * rs + 1] - mu) * rstd * lw.y + lb.y;
                *(float2*)&out[(size_t)(m0 + rloc) * 256 + col] = o;
            }
        }
    }
}

// ---------------------------------------------------------------------------
extern "C" void kernel_launch(void* const* d_in, const int* in_sizes, int n_in,
                              void* d_out, int out_size)
{
    const float* q    = (const float*)d_in[0];
    const float* k    = (const float*)d_in[1];
    const float* v    = (const float*)d_in[2];
    const float* Wq   = (const float*)d_in[3];
    const float* bq   = (const float*)d_in[4];
    const float* Wk   = (const float*)d_in[5];
    const float* bk   = (const float*)d_in[6];
    const float* Wv   = (const float*)d_in[7];
    const float* bv   = (const float*)d_in[8];
    const float* Wfc  = (const float*)d_in[9];
    const float* bfc  = (const float*)d_in[10];
    const float* ln_w = (const float*)d_in[11];
    const float* ln_b = (const float*)d_in[12];

    float* out  = (float*)d_out;
    float* attn = out + OUT_ELEMS;

    static bool attr_set = false;
    if (!attr_set) {
        cudaFuncSetAttribute(gemm_proj,    cudaFuncAttributeMaxDynamicSharedMemorySize, GP_SMEM_BYTES);
        cudaFuncSetAttribute(attn_kernel,  cudaFuncAttributeMaxDynamicSharedMemorySize, ATTN_SMEM_BYTES);
        cudaFuncSetAttribute(fc_ln_kernel, cudaFuncAttributeMaxDynamicSharedMemorySize, FC_SMEM_BYTES);
        attr_set = true;
    }

    wconv<<<256, 256>>>(Wq, Wk, Wv, Wfc);
    gemm_proj<<<dim3(512, 2, 3), 256, GP_SMEM_BYTES>>>(q, k, v, bq, bk, bv);
    attn_kernel<<<NBLH, 256, ATTN_SMEM_BYTES>>>(attn);
    fc_ln_kernel<<<512, 512, FC_SMEM_BYTES>>>(bfc, q, ln_w, ln_b, out);
}

// round 5
// speedup vs baseline: 4.1413x; 1.3843x over previous
#include <cuda_runtime.h>
#include <cuda_fp16.h>
#include <math.h>
#include <stdint.h>

typedef uint32_t u32;

#define MROWS 65536
#define NBLH  4096
#define OUT_ELEMS ((size_t)MROWS * 256)

// Scratch: fp16 pairs packed in u32 words (pairs along the k/d dimension)
__device__ u32 g_qh[(size_t)NBLH * 128 * 16];   // [blq][h][w][dk/2]
__device__ u32 g_kh[(size_t)NBLH * 128 * 16];
__device__ u32 g_vh[(size_t)NBLH * 128 * 16];
__device__ u32 g_attnout[(size_t)MROWS * 128];  // [m][d/2]
__device__ u32 g_wh[4 * 32768];                 // Wq,Wk,Wv,Wfc as fp16 pairs [n][k/2]

// ---------------------------------------------------------------------------
// helpers
// ---------------------------------------------------------------------------
__device__ __forceinline__ u32 f2h2(float lo, float hi) {
    __half2 h = __floats2half2_rn(lo, hi);
    return *reinterpret_cast<u32*>(&h);
}
__device__ __forceinline__ void mma_f16(float* d, const u32* a, u32 b0, u32 b1) {
    asm volatile(
        "mma.sync.aligned.m16n8k16.row.col.f32.f16.f16.f32 "
        "{%0,%1,%2,%3}, {%4,%5,%6,%7}, {%8,%9}, {%0,%1,%2,%3};"
        : "+f"(d[0]), "+f"(d[1]), "+f"(d[2]), "+f"(d[3])
        : "r"(a[0]), "r"(a[1]), "r"(a[2]), "r"(a[3]), "r"(b0), "r"(b1));
}
__device__ __forceinline__ void ldmx4(u32* r, u32 addr) {
    asm volatile("ldmatrix.sync.aligned.m8n8.x4.shared.b16 {%0,%1,%2,%3}, [%4];"
        : "=r"(r[0]), "=r"(r[1]), "=r"(r[2]), "=r"(r[3]) : "r"(addr));
}
__device__ __forceinline__ void ldmx4t(u32* r, u32 addr) {
    asm volatile("ldmatrix.sync.aligned.m8n8.x4.trans.shared.b16 {%0,%1,%2,%3}, [%4];"
        : "=r"(r[0]), "=r"(r[1]), "=r"(r[2]), "=r"(r[3]) : "r"(addr));
}
__device__ __forceinline__ u32 smem_u32(const void* p) {
    u32 a;
    asm("{ .reg .u64 t; cvta.to.shared.u64 t, %1; cvt.u32.u64 %0, t; }" : "=r"(a) : "l"(p));
    return a;
}
__device__ __forceinline__ void cp16(u32 dst, const void* src) {
    asm volatile("cp.async.cg.shared.global [%0], [%1], 16;" :: "r"(dst), "l"(src));
}
#define CP_COMMIT() asm volatile("cp.async.commit_group;")
#define CP_WAIT(n)  asm volatile("cp.async.wait_group %0;" :: "n"(n))

// row stride in u32 words for all [row][k] smem tiles (16 data + 4 pad)
#define SW 20

// ---------------------------------------------------------------------------
// Weight pre-conversion to packed fp16
// ---------------------------------------------------------------------------
__global__ void wconv(const float* __restrict__ Wq, const float* __restrict__ Wk,
                      const float* __restrict__ Wv, const float* __restrict__ Wfc)
{
    int i = blockIdx.x * 256 + threadIdx.x;   // 0..32767
    g_wh[i]             = f2h2(Wq[2 * i],  Wq[2 * i + 1]);
    g_wh[32768 + i]     = f2h2(Wk[2 * i],  Wk[2 * i + 1]);
    g_wh[2 * 32768 + i] = f2h2(Wv[2 * i],  Wv[2 * i + 1]);
    g_wh[3 * 32768 + i] = f2h2(Wfc[2 * i], Wfc[2 * i + 1]);
}

// ---------------------------------------------------------------------------
// Kernel A: QKV projection (fp16 mma). Block 128x128, 8 warps (2x4),
// warp tile 64x32, BK=32, 2-stage pipeline (A: ldg+cvt+sts, B: cp.async).
// ---------------------------------------------------------------------------
__global__ __launch_bounds__(256, 2) void gemm_proj(
    const float* __restrict__ q, const float* __restrict__ k, const float* __restrict__ v,
    const float* __restrict__ bq, const float* __restrict__ bk, const float* __restrict__ bv)
{
    __shared__ u32 As[2 * 128 * SW];
    __shared__ u32 Bs[2 * 128 * SW];

    const int z = blockIdx.z;
    const float* X    = (z == 0) ? q : (z == 1) ? k : v;
    const u32*   Wt   = g_wh + (size_t)z * 32768;
    const float* bias = (z == 0) ? bq : (z == 1) ? bk : bv;
    u32*         outp = (z == 0) ? g_qh : (z == 1) ? g_kh : g_vh;
    const float scale = (z == 0) ? 0.17677669529663687f : 1.0f;

    const int tid  = threadIdx.x;
    const int wid  = tid >> 5;
    const int lane = tid & 31;
    const int g    = lane >> 2;
    const int t    = lane & 3;
    const int lr   = lane & 15;
    const int lc   = (lane >> 4) * 4;
    const int wm   = wid >> 2;    // 0..1
    const int wn   = wid & 3;     // 0..3
    const int m0   = blockIdx.x * 128;
    const int n0   = blockIdx.y * 128;

    const u32 as_b = smem_u32(As);
    const u32 bs_b = smem_u32(Bs);

    const int arow  = tid >> 1;      // A ldg: row
    const int ahalf = tid & 1;       // word half (0..7 / 8..15)
    const int brow  = tid >> 2;      // B cp.async: 2 chunks/thread
    const int bc4   = tid & 3;

    float4 fa[4];
    // prologue: A(0) ldg, B(0) cp.async, sts A(0), A(1) ldg, B(1) cp.async
    #pragma unroll
    for (int j = 0; j < 4; j++)
        fa[j] = *(const float4*)&X[(size_t)(m0 + arow) * 256 + ahalf * 16 + j * 4];
    #pragma unroll
    for (int j = 0; j < 2; j++) {
        int idx = tid + j * 256; int r = idx >> 2, c4 = idx & 3;
        cp16(bs_b + (u32)(r * SW + c4 * 4) * 4, &Wt[(size_t)(n0 + r) * 128 + c4 * 4]);
    }
    CP_COMMIT();
    {
        u32* dst = &As[arow * SW + ahalf * 8];
        #pragma unroll
        for (int j = 0; j < 4; j++) {
            dst[2 * j]     = f2h2(fa[j].x, fa[j].y);
            dst[2 * j + 1] = f2h2(fa[j].z, fa[j].w);
        }
    }
    #pragma unroll
    for (int j = 0; j < 4; j++)
        fa[j] = *(const float4*)&X[(size_t)(m0 + arow) * 256 + 32 + ahalf * 16 + j * 4];
    #pragma unroll
    for (int j = 0; j < 2; j++) {
        int idx = tid + j * 256; int r = idx >> 2, c4 = idx & 3;
        cp16(bs_b + (u32)(128 * SW + r * SW + c4 * 4) * 4, &Wt[(size_t)(n0 + r) * 128 + 16 + c4 * 4]);
    }
    CP_COMMIT();

    float acc[4][4][4];
    #pragma unroll
    for (int a = 0; a < 4; a++)
        #pragma unroll
        for (int b = 0; b < 4; b++)
            #pragma unroll
            for (int c = 0; c < 4; c++) acc[a][b][c] = 0.0f;

    for (int i = 0; i < 8; i++) {
        const int s = i & 1;
        if (i < 7) { CP_WAIT(1); } else { CP_WAIT(0); }
        __syncthreads();

        const u32 a0 = as_b + (u32)s * 128 * SW * 4;
        const u32 b0 = bs_b + (u32)s * 128 * SW * 4;
        #pragma unroll
        for (int c = 0; c < 2; c++) {
            u32 ra[4][4];
            #pragma unroll
            for (int mt = 0; mt < 4; mt++)
                ldmx4(ra[mt], a0 + (u32)((wm * 64 + mt * 16 + lr) * SW + c * 8 + lc) * 4);
            #pragma unroll
            for (int qq = 0; qq < 2; qq++) {
                u32 rb[4];
                ldmx4(rb, b0 + (u32)((wn * 32 + qq * 16 + lr) * SW + c * 8 + lc) * 4);
                #pragma unroll
                for (int mt = 0; mt < 4; mt++) {
                    mma_f16(acc[mt][2 * qq],     ra[mt], rb[0], rb[2]);
                    mma_f16(acc[mt][2 * qq + 1], ra[mt], rb[1], rb[3]);
                }
            }
        }

        if (i < 7) {
            u32* dst = &As[(s ^ 1) * 128 * SW + arow * SW + ahalf * 8];
            #pragma unroll
            for (int j = 0; j < 4; j++) {
                dst[2 * j]     = f2h2(fa[j].x, fa[j].y);
                dst[2 * j + 1] = f2h2(fa[j].z, fa[j].w);
            }
        }
        __syncthreads();
        if (i < 6) {
            #pragma unroll
            for (int j = 0; j < 4; j++)
                fa[j] = *(const float4*)&X[(size_t)(m0 + arow) * 256 + (i + 2) * 32 + ahalf * 16 + j * 4];
            #pragma unroll
            for (int j = 0; j < 2; j++) {
                int idx = tid + j * 256; int r = idx >> 2, c4 = idx & 3;
                cp16(bs_b + (u32)(s * 128 * SW + r * SW + c4 * 4) * 4,
                     &Wt[(size_t)(n0 + r) * 128 + (i + 2) * 16 + c4 * 4]);
            }
            CP_COMMIT();
        }
    }

    // epilogue: bias, scale, pack fp16 pairs, scatter to [blq][h][w][dk/2]
    #pragma unroll
    for (int mt = 0; mt < 4; mt++) {
        #pragma unroll
        for (int nt = 0; nt < 4; nt++) {
            int n  = n0 + wn * 32 + nt * 8 + 2 * t;
            int h  = n >> 5;
            int dw = (n & 31) >> 1;
            float b0v = bias[n], b1v = bias[n + 1];
            #pragma unroll
            for (int rs = 0; rs < 2; rs++) {
                int m   = m0 + wm * 64 + mt * 16 + g + 8 * rs;
                int blq = m >> 7;
                int ww  = m & 127;
                outp[(((size_t)blq * 8 + h) * 128 + ww) * 16 + dw] =
                    f2h2((acc[mt][nt][2 * rs]     + b0v) * scale,
                         (acc[mt][nt][2 * rs + 1] + b1v) * scale);
            }
        }
    }
}

// ---------------------------------------------------------------------------
// Kernel B: attention per (b,l,h), fp16 mma + ldmatrix.
// smem 30KB -> high occupancy. PV A-fragments come straight from sacc (packed).
// ---------------------------------------------------------------------------
__global__ __launch_bounds__(256, 2) void attn_kernel(float* __restrict__ attn_out)
{
    __shared__ u32 Qs[128 * SW];
    __shared__ u32 Ks[128 * SW];
    __shared__ u32 Vs[128 * SW];

    const int blk  = blockIdx.x;
    const int tid  = threadIdx.x;
    const int wid  = tid >> 5;
    const int lane = tid & 31;
    const int g    = lane >> 2;
    const int t    = lane & 3;
    const int lr   = lane & 15;
    const int lc   = (lane >> 4) * 4;

    const u32 qs_b = smem_u32(Qs);
    const u32 ks_b = smem_u32(Ks);
    const u32 vs_b = smem_u32(Vs);

    const uint4* Qg = (const uint4*)(g_qh + (size_t)blk * 2048);
    const uint4* Kg = (const uint4*)(g_kh + (size_t)blk * 2048);
    const uint4* Vg = (const uint4*)(g_vh + (size_t)blk * 2048);

    #pragma unroll
    for (int j = 0; j < 2; j++) {
        int idx = tid + j * 256;        // uint4 index 0..511
        int row = idx >> 2, q4 = idx & 3;
        *(uint4*)&Qs[row * SW + q4 * 4] = Qg[idx];
        *(uint4*)&Ks[row * SW + q4 * 4] = Kg[idx];
        *(uint4*)&Vs[row * SW + q4 * 4] = Vg[idx];
    }
    __syncthreads();

    // S = Q K^T : 16 rows x 128 cols per warp
    float sacc[16][4];
    #pragma unroll
    for (int nt = 0; nt < 16; nt++)
        #pragma unroll
        for (int c = 0; c < 4; c++) sacc[nt][c] = 0.0f;

    const int rbase16 = wid * 16;
    const int rbase   = rbase16 + g;
    #pragma unroll
    for (int c = 0; c < 2; c++) {
        u32 ra[4];
        ldmx4(ra, qs_b + (u32)((rbase16 + lr) * SW + c * 8 + lc) * 4);
        #pragma unroll
        for (int qq = 0; qq < 8; qq++) {
            u32 rb[4];
            ldmx4(rb, ks_b + (u32)((qq * 16 + lr) * SW + c * 8 + lc) * 4);
            mma_f16(sacc[2 * qq],     ra, rb[0], rb[2]);
            mma_f16(sacc[2 * qq + 1], ra, rb[1], rb[3]);
        }
    }

    // softmax (rows shared within lane quads via xor 1,2)
    float inv[2];
    #pragma unroll
    for (int rs = 0; rs < 2; rs++) {
        float mx = -1e30f;
        #pragma unroll
        for (int nt = 0; nt < 16; nt++) {
            mx = fmaxf(mx, sacc[nt][2 * rs]);
            mx = fmaxf(mx, sacc[nt][2 * rs + 1]);
        }
        mx = fmaxf(mx, __shfl_xor_sync(0xffffffffu, mx, 1));
        mx = fmaxf(mx, __shfl_xor_sync(0xffffffffu, mx, 2));
        float s = 0.0f;
        #pragma unroll
        for (int nt = 0; nt < 16; nt++) {
            float e0 = __expf(sacc[nt][2 * rs] - mx);
            float e1 = __expf(sacc[nt][2 * rs + 1] - mx);
            sacc[nt][2 * rs] = e0; sacc[nt][2 * rs + 1] = e1;
            s += e0 + e1;
        }
        s += __shfl_xor_sync(0xffffffffu, s, 1);
        s += __shfl_xor_sync(0xffffffffu, s, 2);
        inv[rs] = 1.0f / s;
    }
    #pragma unroll
    for (int nt = 0; nt < 16; nt++) {
        sacc[nt][0] *= inv[0]; sacc[nt][1] *= inv[0];
        sacc[nt][2] *= inv[1]; sacc[nt][3] *= inv[1];
    }

    // write attn probs (fp32)
    const size_t abase = (size_t)blk * 16384;
    #pragma unroll
    for (int nt = 0; nt < 16; nt++) {
        int col = nt * 8 + 2 * t;
        float2 p0; p0.x = sacc[nt][0]; p0.y = sacc[nt][1];
        float2 p1; p1.x = sacc[nt][2]; p1.y = sacc[nt][3];
        *(float2*)&attn_out[abase + (size_t)rbase * 128 + col]       = p0;
        *(float2*)&attn_out[abase + (size_t)(rbase + 8) * 128 + col] = p1;
    }

    // O = P V : A-frags packed from sacc; B via ldmatrix.trans on Vs[j][d]
    float oacc[4][4];
    #pragma unroll
    for (int nt = 0; nt < 4; nt++)
        #pragma unroll
        for (int c = 0; c < 4; c++) oacc[nt][c] = 0.0f;

    const int vrow_off = ((lane >> 3) & 1) * 8 + (lane & 7);
    const int vcol_off = (lane >> 4) * 4;
    #pragma unroll
    for (int ks = 0; ks < 8; ks++) {
        u32 af[4];
        af[0] = f2h2(sacc[2 * ks][0],     sacc[2 * ks][1]);
        af[1] = f2h2(sacc[2 * ks][2],     sacc[2 * ks][3]);
        af[2] = f2h2(sacc[2 * ks + 1][0], sacc[2 * ks + 1][1]);
        af[3] = f2h2(sacc[2 * ks + 1][2], sacc[2 * ks + 1][3]);
        #pragma unroll
        for (int np = 0; np < 2; np++) {
            u32 rb[4];
            ldmx4t(rb, vs_b + (u32)((16 * ks + vrow_off) * SW + np * 8 + vcol_off) * 4);
            mma_f16(oacc[2 * np],     af, rb[0], rb[1]);
            mma_f16(oacc[2 * np + 1], af, rb[2], rb[3]);
        }
    }

    // store O as fp16 pairs to [m][d/2]
    const int blq = blk >> 3;
    const int h   = blk & 7;
    #pragma unroll
    for (int nt = 0; nt < 4; nt++) {
        #pragma unroll
        for (int rs = 0; rs < 2; rs++) {
            int m = blq * 128 + rbase + 8 * rs;
            g_attnout[(size_t)m * 128 + h * 16 + nt * 4 + t] =
                f2h2(oacc[nt][2 * rs], oacc[nt][2 * rs + 1]);
        }
    }
}

// ---------------------------------------------------------------------------
// Kernel C: FC + residual + LayerNorm (fp16 mma, pure cp.async pipeline).
// Block 128x256, 512 threads (16 warps 4x4), warp tile 32x64.
// ---------------------------------------------------------------------------
#define FC_AS_W (2 * 128 * SW)
#define FC_BS_W (2 * 256 * SW)
#define FC_SMEM_BYTES ((FC_AS_W + FC_BS_W + 1024) * 4)

__global__ __launch_bounds__(512, 1) void fc_ln_kernel(
    const float* __restrict__ bfc, const float* __restrict__ resid,
    const float* __restrict__ ln_w, const float* __restrict__ ln_b,
    float* __restrict__ out)
{
    extern __shared__ u32 dyn[];
    u32*  As  = dyn;
    u32*  Bs  = dyn + FC_AS_W;
    float* red = (float*)(dyn + FC_AS_W + FC_BS_W);   // [128][8]

    const u32* Wt = g_wh + 3 * 32768;
    const int tid  = threadIdx.x;
    const int wid  = tid >> 5;
    const int lane = tid & 31;
    const int g    = lane >> 2;
    const int t    = lane & 3;
    const int lr   = lane & 15;
    const int lc   = (lane >> 4) * 4;
    const int wm   = wid >> 2;   // 0..3
    const int wn   = wid & 3;    // 0..3
    const size_t m0 = (size_t)blockIdx.x * 128;

    const u32 as_b = smem_u32(As);
    const u32 bs_b = smem_u32(Bs);

    // prologue: stages 0,1
    #pragma unroll
    for (int st = 0; st < 2; st++) {
        {
            int r = tid >> 2, c4 = tid & 3;   // A: 512 chunks
            cp16(as_b + (u32)(st * 128 * SW + r * SW + c4 * 4) * 4,
                 &g_attnout[(m0 + r) * 128 + st * 16 + c4 * 4]);
        }
        #pragma unroll
        for (int j = 0; j < 2; j++) {         // B: 1024 chunks
            int idx = tid + j * 512; int r = idx >> 2, c4 = idx & 3;
            cp16(bs_b + (u32)(st * 256 * SW + r * SW + c4 * 4) * 4,
                 &Wt[(size_t)r * 128 + st * 16 + c4 * 4]);
        }
        CP_COMMIT();
    }

    float acc[2][8][4];
    #pragma unroll
    for (int a = 0; a < 2; a++)
        #pragma unroll
        for (int b = 0; b < 8; b++)
            #pragma unroll
            for (int c = 0; c < 4; c++) acc[a][b][c] = 0.0f;

    for (int i = 0; i < 8; i++) {
        const int s = i & 1;
        if (i < 7) { CP_WAIT(1); } else { CP_WAIT(0); }
        __syncthreads();

        const u32 a0 = as_b + (u32)s * 128 * SW * 4;
        const u32 b0 = bs_b + (u32)s * 256 * SW * 4;
        #pragma unroll
        for (int c = 0; c < 2; c++) {
            u32 ra[2][4];
            #pragma unroll
            for (int mt = 0; mt < 2; mt++)
                ldmx4(ra[mt], a0 + (u32)((wm * 32 + mt * 16 + lr) * SW + c * 8 + lc) * 4);
            #pragma unroll
            for (int qq = 0; qq < 4; qq++) {
                u32 rb[4];
                ldmx4(rb, b0 + (u32)((wn * 64 + qq * 16 + lr) * SW + c * 8 + lc) * 4);
                #pragma unroll
                for (int mt = 0; mt < 2; mt++) {
                    mma_f16(acc[mt][2 * qq],     ra[mt], rb[0], rb[2]);
                    mma_f16(acc[mt][2 * qq + 1], ra[mt], rb[1], rb[3]);
                }
            }
        }
        __syncthreads();
        if (i < 6) {
            {
                int r = tid >> 2, c4 = tid & 3;
                cp16(as_b + (u32)(s * 128 * SW + r * SW + c4 * 4) * 4,
                     &g_attnout[(m0 + r) * 128 + (i + 2) * 16 + c4 * 4]);
            }
            #pragma unroll
            for (int j = 0; j < 2; j++) {
                int idx = tid + j * 512; int r = idx >> 2, c4 = idx & 3;
                cp16(bs_b + (u32)(s * 256 * SW + r * SW + c4 * 4) * 4,
                     &Wt[(size_t)r * 128 + (i + 2) * 16 + c4 * 4]);
            }
            CP_COMMIT();
        }
    }

    // bias + residual + row stats
    #pragma unroll
    for (int mt = 0; mt < 2; mt++) {
        #pragma unroll
        for (int rs = 0; rs < 2; rs++) {
            int rloc = wm * 32 + mt * 16 + g + 8 * rs;
            float s = 0.0f, sq = 0.0f;
            #pragma unroll
            for (int nt = 0; nt < 8; nt++) {
                int col = wn * 64 + nt * 8 + 2 * t;
                float2 rr = *(const float2*)&resid[(m0 + rloc) * 256 + col];
                float v0 = acc[mt][nt][2 * rs]     + bfc[col]     + rr.x;
                float v1 = acc[mt][nt][2 * rs + 1] + bfc[col + 1] + rr.y;
                acc[mt][nt][2 * rs]     = v0;
                acc[mt][nt][2 * rs + 1] = v1;
                s  += v0 + v1;
                sq += v0 * v0 + v1 * v1;
            }
            s  += __shfl_xor_sync(0xffffffffu, s, 1);
            s  += __shfl_xor_sync(0xffffffffu, s, 2);
            sq += __shfl_xor_sync(0xffffffffu, sq, 1);
            sq += __shfl_xor_sync(0xffffffffu, sq, 2);
            if (t == 0) {
                red[rloc * 8 + wn]     = s;
                red[rloc * 8 + 4 + wn] = sq;
            }
        }
    }
    __syncthreads();

    #pragma unroll
    for (int mt = 0; mt < 2; mt++) {
        #pragma unroll
        for (int rs = 0; rs < 2; rs++) {
            int rloc = wm * 32 + mt * 16 + g + 8 * rs;
            float s  = red[rloc * 8 + 0] + red[rloc * 8 + 1] + red[rloc * 8 + 2] + red[rloc * 8 + 3];
            float sq = red[rloc * 8 + 4] + red[rloc * 8 + 5] + red[rloc * 8 + 6] + red[rloc * 8 + 7];
            float mu   = s * (1.0f / 256.0f);
            float var  = sq * (1.0f / 256.0f) - mu * mu;
            float rstd = rsqrtf(var + 1e-6f);
            #pragma unroll
            for (int nt = 0; nt < 8; nt++) {
                int col = wn * 64 + nt * 8 + 2 * t;
                float2 lw = *(const float2*)&ln_w[col];
                float2 lb = *(const float2*)&ln_b[col];
                float2 o;
                o.x = (acc[mt][nt][2 * rs]     - mu) * rstd * lw.x + lb.x;
                o.y = (acc[mt][nt][2 * rs + 1] - mu) * rstd * lw.y + lb.y;
                *(float2*)&out[(m0 + rloc) * 256 + col] = o;
            }
        }
    }
}

// ---------------------------------------------------------------------------
extern "C" void kernel_launch(void* const* d_in, const int* in_sizes, int n_in,
                              void* d_out, int out_size)
{
    const float* q    = (const float*)d_in[0];
    const float* k    = (const float*)d_in[1];
    const float* v    = (const float*)d_in[2];
    const float* Wq   = (const float*)d_in[3];
    const float* bq   = (const float*)d_in[4];
    const float* Wk   = (const float*)d_in[5];
    const float* bk   = (const float*)d_in[6];
    const float* Wv   = (const float*)d_in[7];
    const float* bv   = (const float*)d_in[8];
    const float* Wfc  = (const float*)d_in[9];
    const float* bfc  = (const float*)d_in[10];
    const float* ln_w = (const float*)d_in[11];
    const float* ln_b = (const float*)d_in[12];

    float* out  = (float*)d_out;
    float* attn = out + OUT_ELEMS;

    static bool attr_set = false;
    if (!attr_set) {
        cudaFuncSetAttribute(fc_ln_kernel, cudaFuncAttributeMaxDynamicSharedMemorySize, FC_SMEM_BYTES);
        attr_set = true;
    }

    wconv<<<128, 256>>>(Wq, Wk, Wv, Wfc);
    gemm_proj<<<dim3(512, 2, 3), 256>>>(q, k, v, bq, bk, bv);
    attn_kernel<<<NBLH, 256>>>(attn);
    fc_ln_kernel<<<512, 512, FC_SMEM_BYTES>>>(bfc, q, ln_w, ln_b, out);
}